// round 8
// baseline (speedup 1.0000x reference)
#include <cuda_runtime.h>
#include <cstddef>

#define NUM_CLASSES 1000000
#define FEAT_DIM    128
#define BATCH       16384
#define ALPHA       0.5f

#define N_ELEMS   ((size_t)NUM_CLASSES * FEAT_DIM)   // 128,000,000
#define N_QUADS   (N_ELEMS / 4)                       // 32,000,000
#define H_QUADS   (N_QUADS / 2)                       // 16,000,000 (copy_A size)
// classes fully written by copy_A: 128*l + 128 <= 4*H_QUADS - 1  ->  l <= 499998
#define L_SPLIT   499999                              // update_lo: l < L_SPLIT

// Scratch. .bss => zero-initialized at load; clean-on-exit in the update
// kernels restores zeroed state for the next graph replay.
__device__ float  g_sums[N_ELEMS];      // 512 MB static bss
__device__ float  g_counts[NUM_CLASSES];
__device__ int    g_owner[BATCH];       // 1 if batch elem is unique owner of its label
__device__ double g_loss;

// ---------------------------------------------------------------------------
// K1 (side stream): scatter features into per-class sums + counts, accumulate
// loss (block-level reduction -> 1 double atomic per block), elect owners.
// One warp per batch element; lane k owns feature quad k.
// ---------------------------------------------------------------------------
__global__ void k_accum(const float* __restrict__ features,
                        const float* __restrict__ centers,
                        const int*   __restrict__ labels)
{
    const int gid  = blockIdx.x * blockDim.x + threadIdx.x;
    const int w    = gid >> 5;
    const int lane = gid & 31;
    const int wib  = threadIdx.x >> 5;

    __shared__ float s_part[8];

    float v = 0.0f;
    if (w < BATCH) {
        const int l = labels[w];
        const float4 f = reinterpret_cast<const float4*>(features)[(size_t)w * 32 + lane];
        const float4 c = reinterpret_cast<const float4*>(centers )[(size_t)l * 32 + lane];

        float* srow = g_sums + (size_t)l * FEAT_DIM + lane * 4;
        atomicAdd(srow + 0, f.x);
        atomicAdd(srow + 1, f.y);
        atomicAdd(srow + 2, f.z);
        atomicAdd(srow + 3, f.w);
        if (lane == 0) {
            const float old = atomicAdd(&g_counts[l], 1.0f);
            g_owner[w] = (old == 0.0f) ? 1 : 0;
        }

        const float dx = f.x - c.x, dy = f.y - c.y, dz = f.z - c.z, dw = f.w - c.w;
        v = dx * dx + dy * dy + dz * dz + dw * dw;
    }

    #pragma unroll
    for (int o = 16; o > 0; o >>= 1)
        v += __shfl_down_sync(0xffffffffu, v, o);
    if (lane == 0) s_part[wib] = v;
    __syncthreads();
    if (threadIdx.x == 0) {
        float tot = 0.0f;
        #pragma unroll
        for (int i = 0; i < 8; i++) tot += s_part[i];
        atomicAdd(&g_loss, (double)tot);
    }
}

// ---------------------------------------------------------------------------
// K2: PURE bulk shifted copy over quad range [base, base+count), dst-aligned
// float4 stores, evict-first hints on the touch-once 1 GB stream. Thread j
// produces out quad j = {c[4j-1], c[4j..4j+2]}; straddle element via shfl_up
// (lane 0 scalar-loads it, L2-hot from the adjacent warp's line).
// j==0 (only in the first segment) writes head out[1..3] and tail out[N].
// ---------------------------------------------------------------------------
__global__ void k_copy(const float* __restrict__ c, float* __restrict__ out,
                       size_t base)
{
    const size_t j = base + (size_t)blockIdx.x * blockDim.x + threadIdx.x;
    const float4 b = __ldcs(reinterpret_cast<const float4*>(c) + j);

    float pw = __shfl_up_sync(0xffffffffu, b.w, 1);
    if ((threadIdx.x & 31) == 0 && j > 0)
        pw = __ldg(c + 4 * j - 1);

    if (j == 0) {
        out[1] = b.x; out[2] = b.y; out[3] = b.z;
        out[N_ELEMS] = c[N_ELEMS - 1];               // tail element
    } else {
        __stcs(reinterpret_cast<float4*>(out) + j, make_float4(pw, b.x, b.y, b.z));
    }
}

// ---------------------------------------------------------------------------
// K3: owner warps with label in [lo, hi) overwrite their class row with the
// momentum update, then CLEAR the scratch they consumed. The lo-range variant
// runs concurrent with copy_B (its rows were finished by copy_A).
// emit_loss: thread 0 writes out[0] and resets the accumulator.
//   new_c = (1-ALPHA)*c + (ALPHA/cnt)*sum
// ---------------------------------------------------------------------------
__global__ void k_update(const float* __restrict__ centers,
                         const int*   __restrict__ labels,
                         float*       __restrict__ out,
                         int lo, int hi, int emit_loss)
{
    const int gid  = blockIdx.x * blockDim.x + threadIdx.x;
    const int w    = gid >> 5;
    const int lane = gid & 31;

    if (emit_loss && gid == 0) {
        out[0] = (float)(g_loss / (2.0 * (double)BATCH));
        g_loss = 0.0;
    }
    if (w >= BATCH) return;
    if (!g_owner[w]) return;                 // warp-uniform
    const int l = labels[w];
    if (l < lo || l >= hi) return;           // warp-uniform

    const float cnt = g_counts[l];
    const float k1  = 1.0f - ALPHA;
    const float k2  = ALPHA / fmaxf(cnt, 1.0f);

    const size_t q = (size_t)l * 32 + lane;
    const float4 c = reinterpret_cast<const float4*>(centers)[q];
    const float4 s = reinterpret_cast<const float4*>(g_sums)[q];

    float* o = out + 1 + (size_t)l * FEAT_DIM + lane * 4;
    o[0] = k1 * c.x + k2 * s.x;
    o[1] = k1 * c.y + k2 * s.y;
    o[2] = k1 * c.z + k2 * s.z;
    o[3] = k1 * c.w + k2 * s.w;

    // clean-on-exit for the next replay
    reinterpret_cast<float4*>(g_sums)[q] = make_float4(0.f, 0.f, 0.f, 0.f);
    if (lane == 0) {
        g_counts[l] = 0.0f;
        g_owner[w]  = 0;
    }
}

// ---------------------------------------------------------------------------
// Pipelined fork/join (all capture-safe):
//   main:  copy_A ---------> copy_B ----------------> (join) update_hi
//   side:  accum --(wait copy_A)--> update_lo --------^
// update_lo (labels < L_SPLIT, rows finished by copy_A) hides under copy_B;
// only update_hi (~half the rows) remains exposed after the stream ends.
// ---------------------------------------------------------------------------
extern "C" void kernel_launch(void* const* d_in, const int* in_sizes, int n_in,
                              void* d_out, int out_size)
{
    const float* features = (const float*)d_in[0];
    const float* centers  = (const float*)d_in[1];
    const int*   labels   = (const int*)d_in[2];
    float*       out      = (float*)d_out;

    (void)in_sizes; (void)n_in; (void)out_size;

    const int warps_grid = (BATCH * 32) / 256;          // 2048 blocks of 256
    const int copy_blocks = (int)(H_QUADS / 256);       // 62,500 per half

    int prLo = 0, prHi = 0;
    cudaDeviceGetStreamPriorityRange(&prLo, &prHi);

    cudaStream_t s2;
    cudaEvent_t  eFork, eCopyA, eSide;
    cudaStreamCreateWithPriority(&s2, cudaStreamNonBlocking, prHi);
    cudaEventCreateWithFlags(&eFork,  cudaEventDisableTiming);
    cudaEventCreateWithFlags(&eCopyA, cudaEventDisableTiming);
    cudaEventCreateWithFlags(&eSide,  cudaEventDisableTiming);

    // fork side stream into the capture
    cudaEventRecord(eFork, 0);
    cudaStreamWaitEvent(s2, eFork, 0);

    // side: accumulate (concurrent with copy_A)
    k_accum<<<warps_grid, 256, 0, s2>>>(features, centers, labels);

    // main: first half of the bulk copy
    k_copy<<<copy_blocks, 256>>>(centers, out, 0);
    cudaEventRecord(eCopyA, 0);

    // main: second half of the bulk copy
    k_copy<<<copy_blocks, 256>>>(centers, out, H_QUADS);

    // side: update the low-label rows (finished by copy_A), hidden under copy_B
    cudaStreamWaitEvent(s2, eCopyA, 0);
    k_update<<<warps_grid, 256, 0, s2>>>(centers, labels, out,
                                         0, L_SPLIT, /*emit_loss=*/1);
    cudaEventRecord(eSide, s2);

    // join, then update the high-label rows
    cudaStreamWaitEvent(0, eSide, 0);
    k_update<<<warps_grid, 256>>>(centers, labels, out,
                                  L_SPLIT, NUM_CLASSES, /*emit_loss=*/0);

    cudaEventDestroy(eFork);
    cudaEventDestroy(eCopyA);
    cudaEventDestroy(eSide);
    cudaStreamDestroy(s2);
}

// round 11
// speedup vs baseline: 1.1026x; 1.1026x over previous
#include <cuda_runtime.h>
#include <cstddef>

#define NUM_CLASSES 1000000
#define FEAT_DIM    128
#define BATCH       16384
#define ALPHA       0.5f

#define N_ELEMS   ((size_t)NUM_CLASSES * FEAT_DIM)   // 128,000,000
#define N_QUADS   (N_ELEMS / 4)                       // 32,000,000
#define N_PAIRS   (N_QUADS / 2)                       // 16,000,000 (2 quads/thread)

// Scratch. .bss => zero-initialized at load; clean-on-exit in k_update
// restores zeroed state for the next graph replay.
__device__ float  g_sums[N_ELEMS];      // 512 MB static bss
__device__ float  g_counts[NUM_CLASSES];
__device__ int    g_owner[BATCH];       // 1 if batch elem is unique owner of its label
__device__ double g_loss;

// ---------------------------------------------------------------------------
// K1 (side stream, overlapped with the copy): scatter features into per-class
// sums + counts, accumulate loss (block reduction -> 1 double atomic/block),
// elect one owner warp per distinct label.
// One warp per batch element; lane k owns feature quad k.
// ---------------------------------------------------------------------------
__global__ void k_accum(const float* __restrict__ features,
                        const float* __restrict__ centers,
                        const int*   __restrict__ labels)
{
    const int gid  = blockIdx.x * blockDim.x + threadIdx.x;
    const int w    = gid >> 5;
    const int lane = gid & 31;
    const int wib  = threadIdx.x >> 5;

    __shared__ float s_part[8];

    float v = 0.0f;
    if (w < BATCH) {
        const int l = labels[w];
        const float4 f = reinterpret_cast<const float4*>(features)[(size_t)w * 32 + lane];
        const float4 c = reinterpret_cast<const float4*>(centers )[(size_t)l * 32 + lane];

        float* srow = g_sums + (size_t)l * FEAT_DIM + lane * 4;
        atomicAdd(srow + 0, f.x);
        atomicAdd(srow + 1, f.y);
        atomicAdd(srow + 2, f.z);
        atomicAdd(srow + 3, f.w);
        if (lane == 0) {
            const float old = atomicAdd(&g_counts[l], 1.0f);
            g_owner[w] = (old == 0.0f) ? 1 : 0;
        }

        const float dx = f.x - c.x, dy = f.y - c.y, dz = f.z - c.z, dw = f.w - c.w;
        v = dx * dx + dy * dy + dz * dz + dw * dw;
    }

    #pragma unroll
    for (int o = 16; o > 0; o >>= 1)
        v += __shfl_down_sync(0xffffffffu, v, o);
    if (lane == 0) s_part[wib] = v;
    __syncthreads();
    if (threadIdx.x == 0) {
        float tot = 0.0f;
        #pragma unroll
        for (int i = 0; i < 8; i++) tot += s_part[i];
        atomicAdd(&g_loss, (double)tot);
    }
}

// ---------------------------------------------------------------------------
// K2: PURE bulk shifted copy, 2 quads (32 B) per thread for doubled MLP and
// half the shfl traffic. Thread p owns src quads 2p, 2p+1 and produces dst
// quads 2p, 2p+1:
//   dst[2p]   = { c[8p-1], c[8p..8p+2] }   (straddle from prev thread / shfl)
//   dst[2p+1] = { c[8p+3], c[8p+4..8p+6] } (straddle is local b0.w — free)
// Evict-first hints: the 1 GB stream is touch-once.
// p==0 writes head out[1..3] and tail out[N].
// ---------------------------------------------------------------------------
__global__ void k_copy(const float* __restrict__ c, float* __restrict__ out)
{
    const size_t p  = (size_t)blockIdx.x * blockDim.x + threadIdx.x;  // pair idx
    const float4 b0 = __ldcs(reinterpret_cast<const float4*>(c) + 2 * p);
    const float4 b1 = __ldcs(reinterpret_cast<const float4*>(c) + 2 * p + 1);

    float pw = __shfl_up_sync(0xffffffffu, b1.w, 1);   // prev thread's last elem
    if ((threadIdx.x & 31) == 0 && p > 0)
        pw = __ldg(c + 8 * p - 1);

    if (p == 0) {
        out[1] = b0.x; out[2] = b0.y; out[3] = b0.z;
        out[N_ELEMS] = c[N_ELEMS - 1];                 // tail element
    } else {
        __stcs(reinterpret_cast<float4*>(out) + 2 * p,
               make_float4(pw, b0.x, b0.y, b0.z));
    }
    __stcs(reinterpret_cast<float4*>(out) + 2 * p + 1,
           make_float4(b0.w, b1.x, b1.y, b1.z));
}

// ---------------------------------------------------------------------------
// K3 (after join): owner warps overwrite their class row with the momentum
// update using dst-ALIGNED float4 stores. Lane k computes val = elems
// 4k..4k+3 and stores out quad (32l + k) = {val[4k-1] via shfl, val[4k..4k+2]}
// which covers out[128l+4k .. +3] = row elems 4k-1..4k+2.  [R9 bug was q+1]
// Lane 0 skips the vector store (its quad's first slot is row l-1 elem 127)
// and writes elems 0..2 scalar; lane 31 writes elem 127 scalar. Coverage:
// 0..2 | 3..126 | 127 — complete, disjoint from neighboring rows.
// Then CLEAR the scratch consumed. Thread 0 emits loss + resets accumulator.
//   new_c = (1-ALPHA)*c + (ALPHA/cnt)*sum
// ---------------------------------------------------------------------------
__global__ void k_update(const float* __restrict__ centers,
                         const int*   __restrict__ labels,
                         float*       __restrict__ out)
{
    const int gid  = blockIdx.x * blockDim.x + threadIdx.x;
    const int w    = gid >> 5;
    const int lane = gid & 31;

    if (gid == 0) {
        out[0] = (float)(g_loss / (2.0 * (double)BATCH));
        g_loss = 0.0;
    }
    if (w >= BATCH) return;
    if (!g_owner[w]) return;                 // warp-uniform branch

    const int l = labels[w];
    const float cnt = g_counts[l];
    const float k1  = 1.0f - ALPHA;
    const float k2  = ALPHA / fmaxf(cnt, 1.0f);

    const size_t q = (size_t)l * 32 + lane;
    const float4 c = reinterpret_cast<const float4*>(centers)[q];
    const float4 s = reinterpret_cast<const float4*>(g_sums)[q];

    float4 val;
    val.x = k1 * c.x + k2 * s.x;
    val.y = k1 * c.y + k2 * s.y;
    val.z = k1 * c.z + k2 * s.z;
    val.w = k1 * c.w + k2 * s.w;

    const float pw = __shfl_up_sync(0xffffffffu, val.w, 1);  // val[4k-1]

    const size_t row = 1 + (size_t)l * FEAT_DIM;             // out[] index of elem 0
    if (lane == 0) {
        out[row + 0] = val.x;                                 // elems 0,1,2
        out[row + 1] = val.y;
        out[row + 2] = val.z;
    } else {
        // out quad 32l+k covers out[128l+4k .. +3] = elems 4k-1..4k+2
        reinterpret_cast<float4*>(out)[q] =
            make_float4(pw, val.x, val.y, val.z);
    }
    if (lane == 31)
        out[row + 127] = val.w;                               // elem 127

    // clean-on-exit: restore zeroed scratch for the next replay
    reinterpret_cast<float4*>(g_sums)[q] = make_float4(0.f, 0.f, 0.f, 0.f);
    if (lane == 0) {
        g_counts[l] = 0.0f;
        g_owner[w]  = 0;
    }
}

// ---------------------------------------------------------------------------
// R7 topology (proven best): accum on a high-priority side stream concurrent
// with the single bulk copy; join; one update. All capture-safe.
// ---------------------------------------------------------------------------
extern "C" void kernel_launch(void* const* d_in, const int* in_sizes, int n_in,
                              void* d_out, int out_size)
{
    const float* features = (const float*)d_in[0];
    const float* centers  = (const float*)d_in[1];
    const int*   labels   = (const int*)d_in[2];
    float*       out      = (float*)d_out;

    (void)in_sizes; (void)n_in; (void)out_size;

    const int warps_grid = (BATCH * 32) / 256;          // 2048 blocks of 256

    int prLo = 0, prHi = 0;
    cudaDeviceGetStreamPriorityRange(&prLo, &prHi);

    cudaStream_t s2;
    cudaEvent_t  eFork, eJoin;
    cudaStreamCreateWithPriority(&s2, cudaStreamNonBlocking, prHi);
    cudaEventCreateWithFlags(&eFork, cudaEventDisableTiming);
    cudaEventCreateWithFlags(&eJoin, cudaEventDisableTiming);

    // fork: side stream joins the capture graph via the event dependency
    cudaEventRecord(eFork, 0);
    cudaStreamWaitEvent(s2, eFork, 0);

    k_accum<<<warps_grid, 256, 0, s2>>>(features, centers, labels);     // side
    k_copy <<<(int)(N_PAIRS / 256), 256>>>(centers, out);               // main, 62,500 blocks

    // join: main stream waits for accum before the update
    cudaEventRecord(eJoin, s2);
    cudaStreamWaitEvent(0, eJoin, 0);

    k_update<<<warps_grid, 256>>>(centers, labels, out);

    cudaEventDestroy(eFork);
    cudaEventDestroy(eJoin);
    cudaStreamDestroy(s2);
}